// round 16
// baseline (speedup 1.0000x reference)
#include <cuda_runtime.h>
#include <cuda_bf16.h>
#include <math.h>

// Problem constants
#define B_     64
#define S_     2048
#define D_     768
#define L_     2
#define POOL_  30
#define LEN_   5
#define TOPK_  5
#define SS_    16           // S split count
#define SCHUNK_ (S_ / SS_)  // 128

// Output layout (flattened tuple, fp32):
#define NB_ELEMS   (L_ * B_ * (TOPK_*LEN_) * D_)   // 2457600
#define OFF_SB     0
#define OFF_TB     (NB_ELEMS)
#define OFF_SSIM   (2 * NB_ELEMS)
#define OFF_TSIM   (OFF_SSIM + B_ * POOL_)
#define OFF_SRED   (OFF_TSIM + B_ * POOL_)
#define OFF_TRED   (OFF_SRED + 1)

// Device scratch + flag protocol (all self-resetting per replay)
__device__ float g_partial[SS_ * B_ * D_];   // 3 MB partial sums
__device__ int   g_idx[2][B_ * TOPK_];       // [pool][b*5+k]
__device__ float g_stop[B_];
__device__ float g_ttop[B_];
__device__ int   g_bctr[B_];                 // mean arrivals per batch (16)
__device__ int   g_ready[B_];                // batch-b partials complete
__device__ int   g_rdone[B_];                // sims consumers per batch (2)
__device__ int   g_simflag[2 * B_];          // (pool,b) indices ready
__device__ int   g_gctr[2 * B_];             // gather consumers per flag (10)
__device__ int   g_alldone;                  // sims completion (128)

// ---------------------------------------------------------------------------
// Kernel A: partial mean; PDL trigger at START so dependents co-schedule.
// Real dependency is the per-batch flag protocol at the end.
// ---------------------------------------------------------------------------
__global__ void __launch_bounds__(192) k_mean_partial(const float* __restrict__ x) {
    cudaTriggerProgrammaticLaunchCompletion();
    int b  = blockIdx.x;
    int ss = blockIdx.y;
    int d4 = threadIdx.x;                     // 0..191, each owns 4 d's
    const float4* xp = reinterpret_cast<const float4*>(x)
                     + ((size_t)(b * S_ + ss * SCHUNK_)) * (D_ / 4) + d4;
    float4 acc = make_float4(0.f, 0.f, 0.f, 0.f);
#pragma unroll 16
    for (int s = 0; s < SCHUNK_; ++s) {
        float4 v = __ldcs(&xp[(size_t)s * (D_ / 4)]);
        acc.x += v.x; acc.y += v.y; acc.z += v.z; acc.w += v.w;
    }
    reinterpret_cast<float4*>(g_partial)[(ss * B_ + b) * (D_ / 4) + d4] = acc;

    __threadfence();
    __syncthreads();
    if (threadIdx.x == 0) {
        int old = atomicAdd(&g_bctr[b], 1);
        if (old == SS_ - 1) {
            atomicExch(&g_bctr[b], 0);        // reset for next replay
            __threadfence();
            atomicExch(&g_ready[b], 1);       // publish: batch b ready
        }
    }
}

// ---------------------------------------------------------------------------
// Kernel B: sims + top-5 per (pool, batch). grid 128, block 192 (6 warps).
// Spins on g_ready[b]; processes batches as they complete, overlapping mean.
// ---------------------------------------------------------------------------
__global__ void __launch_bounds__(192) k_sims(const float* __restrict__ skey,
                                              const float* __restrict__ tkey,
                                              float* __restrict__ out) {
    cudaTriggerProgrammaticLaunchCompletion();   // let gather co-schedule

    __shared__ __align__(16) float xn[D_];
    __shared__ float sim[POOL_];
    __shared__ float red[8];

    const int pool = blockIdx.x >> 6;         // 0 = s, 1 = t
    const int b    = blockIdx.x & 63;
    const float* keys = pool ? tkey : skey;
    const int simoff  = pool ? OFF_TSIM : OFF_SSIM;

    // Wait for this batch's partials (device flag, not grid sync).
    if (threadIdx.x == 0) {
        while (atomicAdd(&g_ready[b], 0) == 0) __nanosleep(256);
    }
    __syncthreads();
    __threadfence();                          // acquire: see mean's stores

    const int d4 = threadIdx.x;
    float sq;
    {
        float4 s = make_float4(0.f, 0.f, 0.f, 0.f);
#pragma unroll
        for (int s2 = 0; s2 < SS_; ++s2) {
            float4 v = __ldcg(&reinterpret_cast<const float4*>(g_partial)[(s2 * B_ + b) * (D_ / 4) + d4]);
            s.x += v.x; s.y += v.y; s.z += v.z; s.w += v.w;
        }
        const float scale = 1.f / (float)S_;
        s.x *= scale; s.y *= scale; s.z *= scale; s.w *= scale;
        reinterpret_cast<float4*>(xn)[d4] = s;
        sq = s.x * s.x + s.y * s.y + s.z * s.z + s.w * s.w;
    }

    // block reduce over 6 warps
    const int lane = threadIdx.x & 31, w = threadIdx.x >> 5;
#pragma unroll
    for (int o = 16; o; o >>= 1) sq += __shfl_down_sync(0xffffffffu, sq, o);
    if (lane == 0) red[w] = sq;
    __syncthreads();
    if (w == 0) {
        float v = (lane < 6) ? red[lane] : 0.f;
#pragma unroll
        for (int o = 4; o; o >>= 1) v += __shfl_down_sync(0xffffffffu, v, o);
        if (lane == 0) red[0] = v;
    }
    __syncthreads();
    const float inv = rsqrtf(fmaxf(red[0], 1e-12f));
    {
        float4 v = reinterpret_cast<float4*>(xn)[d4];
        v.x *= inv; v.y *= inv; v.z *= inv; v.w *= inv;
        reinterpret_cast<float4*>(xn)[d4] = v;
    }
    __syncthreads();

    // 30 dots: warp per key round-robin (6 warps x 5 keys); inline key norm
    for (int key = w; key < POOL_; key += 6) {
        const float* kp = keys + key * D_;
        float dot = 0.f, kk = 0.f;
#pragma unroll
        for (int i = 0; i < D_ / 32; ++i) {
            int d = lane + i * 32;
            float kv = __ldg(&kp[d]);
            dot += kv * xn[d];
            kk  += kv * kv;
        }
#pragma unroll
        for (int o = 16; o; o >>= 1) {
            dot += __shfl_down_sync(0xffffffffu, dot, o);
            kk  += __shfl_down_sync(0xffffffffu, kk, o);
        }
        if (lane == 0) {
            float sv = dot * rsqrtf(fmaxf(kk, 1e-12f));
            sim[key] = sv;
            out[simoff + b * POOL_ + key] = sv;
        }
    }
    __syncthreads();

    // top-5 (thread 0); strict '>' keeps lowest index on ties
    if (threadIdx.x == 0) {
        float loc[POOL_];
#pragma unroll
        for (int i = 0; i < POOL_; ++i) loc[i] = sim[i];
        float topsum = 0.f;
#pragma unroll
        for (int k = 0; k < TOPK_; ++k) {
            int   bj = 0;
            float bv = loc[0];
#pragma unroll
            for (int i = 1; i < POOL_; ++i) {
                if (loc[i] > bv) { bv = loc[i]; bj = i; }
            }
            g_idx[pool][b * TOPK_ + k] = bj;
            topsum += bv;
            loc[bj] = -INFINITY;
        }
        if (pool == 0) g_stop[b] = topsum; else g_ttop[b] = topsum;
        __threadfence();

        // consume g_ready (2 consumers per batch; 2nd resets)
        int o1 = atomicAdd(&g_rdone[b], 1);
        if (o1 == 1) { atomicExch(&g_rdone[b], 0); atomicExch(&g_ready[b], 0); }

        // publish indices for gather
        atomicExch(&g_simflag[pool * B_ + b], 1);

        // 128th sims block computes both scalars
        int a = atomicAdd(&g_alldone, 1);
        if (a == 2 * B_ - 1) {
            atomicExch(&g_alldone, 0);
            __threadfence();
            float s0 = 0.f, s1 = 0.f;
            for (int i = 0; i < B_; ++i) {
                s0 += __ldcg(&g_stop[i]);
                s1 += __ldcg(&g_ttop[i]);
            }
            out[OFF_SRED] = s0 / (float)B_;
            out[OFF_TRED] = s1 / (float)B_;
        }
    }
}

// ---------------------------------------------------------------------------
// Kernel C: gather. grid 1280 = (pool 2) x (b 64) x (l 2) x (k 5), block 192.
// Spins on its (pool,b) flag; 10 consumer blocks per flag, 10th resets.
// ---------------------------------------------------------------------------
__global__ void __launch_bounds__(192) k_gather(const float* __restrict__ sp,
                                                const float* __restrict__ tp,
                                                float* __restrict__ out) {
    const int bi   = blockIdx.x;
    const int k    = bi % TOPK_;
    const int l    = (bi / TOPK_) % L_;
    const int b    = (bi / (TOPK_ * L_)) % B_;
    const int pool = bi / (TOPK_ * L_ * B_);
    const int pb   = pool * B_ + b;

    if (threadIdx.x == 0) {
        while (atomicAdd(&g_simflag[pb], 0) == 0) __nanosleep(512);
    }
    __syncthreads();
    __threadfence();                          // acquire: see g_idx

    const int idx = __ldcg(&g_idx[pool][b * TOPK_ + k]);
    const float* prompts = pool ? tp : sp;
    float* outb = out + (pool ? OFF_TB : OFF_SB);

    const int ROWF4 = D_ / 4;   // 192
    const int col = threadIdx.x;
    const float4* src = reinterpret_cast<const float4*>(
        prompts + ((size_t)((l * POOL_ + idx) * LEN_)) * D_) + col;
    float4* dst = reinterpret_cast<float4*>(
        outb + ((size_t)((l * B_ + b) * (TOPK_ * LEN_) + k * LEN_)) * D_) + col;
#pragma unroll
    for (int t = 0; t < LEN_; ++t) {
        __stcs(&dst[t * ROWF4], __ldg(&src[t * ROWF4]));
    }

    // consume flag (10 consumers; 10th resets for next replay)
    __syncthreads();
    if (threadIdx.x == 0) {
        int o = atomicAdd(&g_gctr[pb], 1);
        if (o == L_ * TOPK_ - 1) {
            atomicExch(&g_gctr[pb], 0);
            atomicExch(&g_simflag[pb], 0);
        }
    }
}

// ---------------------------------------------------------------------------
// Launch: mean (triggers at start) -> sims (PDL) -> gather (PDL)
// ---------------------------------------------------------------------------
static void launch_pdl(void* fn, dim3 grid, dim3 block, void** args) {
    cudaLaunchConfig_t cfg = {};
    cfg.gridDim = grid;
    cfg.blockDim = block;
    cfg.dynamicSmemBytes = 0;
    cfg.stream = 0;
    cudaLaunchAttribute attr[1];
    attr[0].id = cudaLaunchAttributeProgrammaticStreamSerialization;
    attr[0].val.programmaticStreamSerializationAllowed = 1;
    cfg.attrs = attr;
    cfg.numAttrs = 1;
    cudaLaunchKernelExC(&cfg, fn, args);
}

extern "C" void kernel_launch(void* const* d_in, const int* in_sizes, int n_in,
                              void* d_out, int out_size) {
    (void)in_sizes; (void)n_in; (void)out_size;
    const float* x_embed  = (const float*)d_in[0];
    const float* s_prompt = (const float*)d_in[1];
    const float* t_prompt = (const float*)d_in[2];
    const float* s_key    = (const float*)d_in[3];
    const float* t_key    = (const float*)d_in[4];
    float* out = (float*)d_out;

    k_mean_partial<<<dim3(B_, SS_), 192>>>(x_embed);
    {
        void* args[] = { (void*)&s_key, (void*)&t_key, (void*)&out };
        launch_pdl((void*)k_sims, dim3(2 * B_), dim3(192), args);
    }
    {
        void* args[] = { (void*)&s_prompt, (void*)&t_prompt, (void*)&out };
        launch_pdl((void*)k_gather, dim3(2 * B_ * L_ * TOPK_), dim3(192), args);
    }
}